// round 2
// baseline (speedup 1.0000x reference)
#include <cuda_runtime.h>

// Max-unpool 2x2 stride 2, NHWC.
// x:      [16, 128, 128, 256] f32   (read once)
// pooled: [16,  64,  64, 256] f32   (read once)
// out:    [16, 128, 128, 256] f32   (write once)
// Pure streaming -> use evict-first (.cs) cache policy everywhere.

static constexpr int N_  = 16;
static constexpr int H_  = 128;
static constexpr int W_  = 128;
static constexpr int C_  = 256;
static constexpr int HP_ = H_ / 2;
static constexpr int WP_ = W_ / 2;
static constexpr int C4_ = C_ / 4;            // 64 float4 per channel row
static constexpr int ROW4_ = W_ * C4_;        // x row stride in float4 (8192)
// Each thread handles 2 consecutive float4 chunks (8 channels) of one window.
static constexpr int C8_ = C4_ / 2;           // 32 pairs per channel row
static constexpr int TOTAL8 = N_ * HP_ * WP_ * C8_;  // 2,097,152 threads

__device__ __forceinline__ void unpool4(const float4& v00, const float4& v01,
                                        const float4& v10, const float4& v11,
                                        const float4& pv,
                                        float4& o00, float4& o01,
                                        float4& o10, float4& o11)
{
    const float* a0 = &v00.x;
    const float* a1 = &v01.x;
    const float* a2 = &v10.x;
    const float* a3 = &v11.x;
    const float* pp = &pv.x;
    float* r0 = &o00.x;
    float* r1 = &o01.x;
    float* r2 = &o10.x;
    float* r3 = &o11.x;
    #pragma unroll
    for (int l = 0; l < 4; ++l) {
        float best = a0[l];
        int bi = 0;
        if (a1[l] > best) { best = a1[l]; bi = 1; }
        if (a2[l] > best) { best = a2[l]; bi = 2; }
        if (a3[l] > best) {              bi = 3; }
        float val = fmaxf(pp[l], 0.0f);
        r0[l] = (bi == 0) ? val : 0.0f;
        r1[l] = (bi == 1) ? val : 0.0f;
        r2[l] = (bi == 2) ? val : 0.0f;
        r3[l] = (bi == 3) ? val : 0.0f;
    }
}

__global__ __launch_bounds__(256)
void unpool_kernel(const float4* __restrict__ x,
                   const float4* __restrict__ pooled,
                   float4* __restrict__ out)
{
    int i = blockIdx.x * blockDim.x + threadIdx.x;
    if (i >= TOTAL8) return;

    // i -> ((n*HP + hp)*WP + wp)*C8 + c8 ; chunk = 2 float4s at c4 = 2*c8
    int c8 = i & (C8_ - 1);
    int t  = i >> 5;            // / C8_
    int wp = t & (WP_ - 1);
    t >>= 6;                    // / WP_
    int hp = t & (HP_ - 1);
    int n  = t >> 6;            // / HP_

    int c4   = c8 * 2;
    int base = ((n * H_ + 2 * hp) * W_ + 2 * wp) * C4_ + c4;
    int pidx = ((n * HP_ + hp) * WP_ + wp) * C4_ + c4;

    // Front-batched streaming loads (evict-first).
    float4 v00a = __ldcs(x + base);
    float4 v00b = __ldcs(x + base + 1);
    float4 v01a = __ldcs(x + base + C4_);
    float4 v01b = __ldcs(x + base + C4_ + 1);
    float4 v10a = __ldcs(x + base + ROW4_);
    float4 v10b = __ldcs(x + base + ROW4_ + 1);
    float4 v11a = __ldcs(x + base + ROW4_ + C4_);
    float4 v11b = __ldcs(x + base + ROW4_ + C4_ + 1);
    float4 pva  = __ldcs(pooled + pidx);
    float4 pvb  = __ldcs(pooled + pidx + 1);

    float4 o00a, o01a, o10a, o11a;
    float4 o00b, o01b, o10b, o11b;
    unpool4(v00a, v01a, v10a, v11a, pva, o00a, o01a, o10a, o11a);
    unpool4(v00b, v01b, v10b, v11b, pvb, o00b, o01b, o10b, o11b);

    __stcs(out + base,                 o00a);
    __stcs(out + base + 1,             o00b);
    __stcs(out + base + C4_,           o01a);
    __stcs(out + base + C4_ + 1,       o01b);
    __stcs(out + base + ROW4_,         o10a);
    __stcs(out + base + ROW4_ + 1,     o10b);
    __stcs(out + base + ROW4_ + C4_,   o11a);
    __stcs(out + base + ROW4_ + C4_+1, o11b);
}

extern "C" void kernel_launch(void* const* d_in, const int* in_sizes, int n_in,
                              void* d_out, int out_size)
{
    const float4* x      = (const float4*)d_in[0];
    const float4* pooled = (const float4*)d_in[1];
    float4* out          = (float4*)d_out;

    const int threads = 256;
    const int blocks  = (TOTAL8 + threads - 1) / threads;
    unpool_kernel<<<blocks, threads>>>(x, pooled, out);
}

// round 3
// speedup vs baseline: 1.0396x; 1.0396x over previous
#include <cuda_runtime.h>

// Max-unpool 2x2 stride 2, NHWC. R1 structure (1 float4/thread, occ ~80%)
// + streaming cache hints only (.cs evict-first on all loads/stores).
// x:      [16, 128, 128, 256] f32   (read once)
// pooled: [16,  64,  64, 256] f32   (read once)
// out:    [16, 128, 128, 256] f32   (write once)

static constexpr int N_  = 16;
static constexpr int H_  = 128;
static constexpr int W_  = 128;
static constexpr int C_  = 256;
static constexpr int HP_ = H_ / 2;
static constexpr int WP_ = W_ / 2;
static constexpr int C4_ = C_ / 4;            // 64 float4 per channel row
static constexpr int ROW4_ = W_ * C4_;        // x row stride in float4 (8192)
static constexpr int TOTAL4 = N_ * HP_ * WP_ * C4_;  // 4,194,304

__global__ __launch_bounds__(256)
void unpool_kernel(const float4* __restrict__ x,
                   const float4* __restrict__ pooled,
                   float4* __restrict__ out)
{
    int i = blockIdx.x * blockDim.x + threadIdx.x;
    if (i >= TOTAL4) return;

    // i -> ((n*HP + hp)*WP + wp)*C4 + c4
    int c4 = i & (C4_ - 1);
    int t  = i >> 6;            // / C4_
    int wp = t & (WP_ - 1);
    t >>= 6;                    // / WP_
    int hp = t & (HP_ - 1);
    int n  = t >> 6;            // / HP_

    int base = ((n * H_ + 2 * hp) * W_ + 2 * wp) * C4_ + c4;

    float4 v00 = __ldcs(x + base);
    float4 v01 = __ldcs(x + base + C4_);
    float4 v10 = __ldcs(x + base + ROW4_);
    float4 v11 = __ldcs(x + base + ROW4_ + C4_);
    float4 pv  = __ldcs(pooled + i);

    float a0[4] = {v00.x, v00.y, v00.z, v00.w};
    float a1[4] = {v01.x, v01.y, v01.z, v01.w};
    float a2[4] = {v10.x, v10.y, v10.z, v10.w};
    float a3[4] = {v11.x, v11.y, v11.z, v11.w};
    float p4[4] = {pv.x, pv.y, pv.z, pv.w};

    float o0[4], o1[4], o2[4], o3[4];

    #pragma unroll
    for (int l = 0; l < 4; ++l) {
        float best = a0[l];
        int bi = 0;
        if (a1[l] > best) { best = a1[l]; bi = 1; }
        if (a2[l] > best) { best = a2[l]; bi = 2; }
        if (a3[l] > best) {              bi = 3; }
        float val = fmaxf(p4[l], 0.0f);
        o0[l] = (bi == 0) ? val : 0.0f;
        o1[l] = (bi == 1) ? val : 0.0f;
        o2[l] = (bi == 2) ? val : 0.0f;
        o3[l] = (bi == 3) ? val : 0.0f;
    }

    __stcs(out + base,               make_float4(o0[0], o0[1], o0[2], o0[3]));
    __stcs(out + base + C4_,         make_float4(o1[0], o1[1], o1[2], o1[3]));
    __stcs(out + base + ROW4_,       make_float4(o2[0], o2[1], o2[2], o2[3]));
    __stcs(out + base + ROW4_ + C4_, make_float4(o3[0], o3[1], o3[2], o3[3]));
}

extern "C" void kernel_launch(void* const* d_in, const int* in_sizes, int n_in,
                              void* d_out, int out_size)
{
    const float4* x      = (const float4*)d_in[0];
    const float4* pooled = (const float4*)d_in[1];
    float4* out          = (float4*)d_out;

    const int threads = 256;
    const int blocks  = (TOTAL4 + threads - 1) / threads;
    unpool_kernel<<<blocks, threads>>>(x, pooled, out);
}